// round 1
// baseline (speedup 1.0000x reference)
#include <cuda_runtime.h>
#include <math.h>

// Problem constants
#define BB 4
#define LL 32
#define EE 64
#define CC 96
#define HH 32   // H == W == 32, HW = 1024

// ---------------------------------------------------------------------------
// Device scratch (allocation-free rule: __device__ globals)
// ---------------------------------------------------------------------------
__device__ float  g_s[BB*LL*EE*HH];     // antidiagonal sums        (1 MB)
__device__ float2 g_D[BB*LL*CC*HH];     // spectral state D / y     (3 MB)
__device__ float  g_vhat[BB*LL*EE*HH];  // normalized v             (1 MB)
__device__ float2 g_M[CC*EE];           // Wp1 @ Wb   (complex)
__device__ float2 g_A[EE*CC];           // Wc  @ Wp2  (complex)
__device__ float2 g_lamb[CC*HH];        // lambda[c,u]
__device__ float  g_gam[CC*HH];         // gamma[c,u]
__device__ float2 g_bu0[CC];            // 1024 * (Wp1 @ bb)  (u==0 term)
__device__ float  g_cE[EE];             // Re(Wc @ bp2) + bc_r
__device__ float  g_twc[HH], g_tws[HH]; // cos/sin(2*pi*k/32)

// ---------------------------------------------------------------------------
// K0: fold parameters (tiny)
// ---------------------------------------------------------------------------
__global__ void k0_precomp(const float* __restrict__ Wb_r, const float* __restrict__ Wb_i,
                           const float* __restrict__ bb_r, const float* __restrict__ bb_i,
                           const float* __restrict__ Wp1_r, const float* __restrict__ Wp1_i,
                           const float* __restrict__ Wp2_r, const float* __restrict__ Wp2_i,
                           const float* __restrict__ Wc_r,  const float* __restrict__ Wc_i,
                           const float* __restrict__ bp2_r, const float* __restrict__ bp2_i,
                           const float* __restrict__ bc_r,
                           const float* __restrict__ params_log)
{
    int blk = blockIdx.x, tid = threadIdx.x;
    if (blk < CC) {
        int c = blk;
        if (tid < EE) {  // M = Wp1 @ Wb  (row c)
            float re = 0.f, im = 0.f;
            for (int k = 0; k < CC; k++) {
                float ar = Wp1_r[c*CC+k], ai = Wp1_i[c*CC+k];
                float br = Wb_r[k*EE+tid], bi = Wb_i[k*EE+tid];
                re += ar*br - ai*bi;
                im += ar*bi + ai*br;
            }
            g_M[c*EE+tid] = make_float2(re, im);
        }
        if (tid < HH) {  // lambda, gamma
            float nu = expf(params_log[c*HH + tid]);
            float th = expf(params_log[(CC + c)*HH + tid]);
            float ga = expf(params_log[(2*CC + c)*HH + tid]);
            float r  = expf(-nu);
            float sn, cs;
            sincosf(th, &sn, &cs);
            g_lamb[c*HH+tid] = make_float2(r*cs, r*sn);
            g_gam [c*HH+tid] = ga;
        }
        if (tid == 0) {  // 1024 * (Wp1 @ bb)[c]
            float re = 0.f, im = 0.f;
            for (int k = 0; k < CC; k++) {
                float ar = Wp1_r[c*CC+k], ai = Wp1_i[c*CC+k];
                re += ar*bb_r[k] - ai*bb_i[k];
                im += ar*bb_i[k] + ai*bb_r[k];
            }
            g_bu0[c] = make_float2(1024.f*re, 1024.f*im);
        }
    } else if (blk < CC + EE) {
        int e = blk - CC;
        if (tid < CC) {  // A = Wc @ Wp2  (row e)
            float re = 0.f, im = 0.f;
            for (int k = 0; k < CC; k++) {
                float ar = Wc_r[e*CC+k], ai = Wc_i[e*CC+k];
                float br = Wp2_r[k*CC+tid], bi = Wp2_i[k*CC+tid];
                re += ar*br - ai*bi;
                im += ar*bi + ai*br;
            }
            g_A[e*CC+tid] = make_float2(re, im);
        }
        if (tid == 0) {  // constE[e] = Re(Wc@bp2)[e] + bc_r[e]
            float acc = bc_r[e];
            for (int c = 0; c < CC; c++)
                acc += Wc_r[e*CC+c]*bp2_r[c] - Wc_i[e*CC+c]*bp2_i[c];
            g_cE[e] = acc;
        }
    } else {
        if (tid < HH) {  // twiddles cos/sin(2*pi*k/32) = pi*k/16
            float sn, cs;
            sincospif((float)tid / 16.0f, &sn, &cs);
            g_twc[tid] = cs; g_tws[tid] = sn;
        }
    }
}

// ---------------------------------------------------------------------------
// K1: antidiagonal sums  s[b,l,e,m] = sum_{(p+q)%32==m} x[b,l,e,p,q]
// One warp per (b,l,e) tile. Lane m reads the rotated row -> fully coalesced.
// ---------------------------------------------------------------------------
__global__ __launch_bounds__(256) void k1_adiag(const float* __restrict__ x)
{
    int w    = blockIdx.x * 8 + (threadIdx.x >> 5);   // 0..8191
    int lane = threadIdx.x & 31;
    const float* xp = x + (size_t)w * 1024;
    float acc = 0.f;
    #pragma unroll
    for (int p = 0; p < 32; p++)
        acc += xp[p*32 + ((lane - p) & 31)];
    g_s[w*32 + lane] = acc;
}

// ---------------------------------------------------------------------------
// K2: per (b,l):  t[c,m] = sum_e M[c,e]*s[e,m]   (complex * real)
//                 T[c,u] = DFT32(t[c,:])[u]      (e^{-i 2pi um/32})
//                 D[c,u] = gamma[c,u]*(T + bp1[c] + (u==0)*1024*(Wp1@bb)[c])
// ---------------------------------------------------------------------------
__global__ __launch_bounds__(256) void k2_mix_dft(const float* __restrict__ bp1_r,
                                                  const float* __restrict__ bp1_i)
{
    __shared__ float  s_sh[EE*32];
    __shared__ float2 t_sh[CC*32];
    __shared__ float  twc[32], tws[32];
    int bl = blockIdx.x, tid = threadIdx.x;

    for (int i = tid; i < EE*32; i += 256) s_sh[i] = g_s[bl*EE*32 + i];
    if (tid < 32) { twc[tid] = g_twc[tid]; tws[tid] = g_tws[tid]; }
    __syncthreads();

    // phase A: channel mix (real s, complex M)
    #pragma unroll
    for (int k = 0; k < 12; k++) {
        int o = tid + k*256;            // o = c*32 + m  (warp-uniform c)
        int c = o >> 5, m = o & 31;
        float re = 0.f, im = 0.f;
        #pragma unroll 16
        for (int e = 0; e < EE; e++) {
            float  sv = s_sh[e*32 + m];
            float2 M  = g_M[c*EE + e];
            re += M.x * sv;
            im += M.y * sv;
        }
        t_sh[o] = make_float2(re, im);
    }
    __syncthreads();

    // phase B: length-32 DFT + biases + gamma
    #pragma unroll
    for (int k = 0; k < 12; k++) {
        int o = tid + k*256;
        int c = o >> 5, u = o & 31;
        float re = 0.f, im = 0.f;
        #pragma unroll 8
        for (int m = 0; m < 32; m++) {
            float2 t = t_sh[c*32 + m];
            int idx = (u*m) & 31;
            float cw = twc[idx], sw = tws[idx];
            re += t.x*cw + t.y*sw;      // (t)(cos - i sin)
            im += t.y*cw - t.x*sw;
        }
        re += bp1_r[c]; im += bp1_i[c];
        if (u == 0) { float2 b = g_bu0[c]; re += b.x; im += b.y; }
        float ga = g_gam[c*32 + u];
        g_D[(bl*CC + c)*32 + u] = make_float2(re*ga, im*ga);
    }
}

// ---------------------------------------------------------------------------
// K3: LRU scan over L (in place on g_D):  y[l] = D[l] + lamb * mask[l-1] * y[l-1]
// One thread per (b,c,u): 12288 threads.
// ---------------------------------------------------------------------------
__global__ __launch_bounds__(256) void k3_scan(const float* __restrict__ mask)
{
    int t = blockIdx.x*256 + threadIdx.x;   // 0..12287
    int u = t & 31;
    int c = (t >> 5) % CC;
    int b = t / (CC*32);
    float2 lam = g_lamb[c*32 + u];
    float2 y   = make_float2(0.f, 0.f);
    for (int l = 0; l < LL; l++) {
        int idx  = ((b*LL + l)*CC + c)*32 + u;
        float2 d = g_D[idx];
        float mp = (l == 0) ? 0.f : mask[b*LL + l - 1];
        float yr = mp*y.x, yi = mp*y.y;
        y.x = d.x + lam.x*yr - lam.y*yi;
        y.y = d.y + lam.x*yi + lam.y*yr;
        g_D[idx] = y;
    }
}

// ---------------------------------------------------------------------------
// K4: per (b,l):  g[c,m] = (1/1024) * sum_u y[c,u] e^{+i 2pi um/32}
//                 v[e,m] = Re(sum_c A[e,c] g[c,m]) + constE[e]
//                 LN stats over 2048 v's (each appears 32x in full tensor)
//                 vhat = (v - mu) * rstd
// ---------------------------------------------------------------------------
__global__ __launch_bounds__(256) void k4_idft_ln()
{
    __shared__ float2 y_sh[CC*32];          // reused for g after phase A
    __shared__ float  twc[32], tws[32];
    __shared__ float  red[16];
    int bl = blockIdx.x, tid = threadIdx.x;

    for (int i = tid; i < CC*32; i += 256) y_sh[i] = g_D[bl*CC*32 + i];
    if (tid < 32) { twc[tid] = g_twc[tid]; tws[tid] = g_tws[tid]; }
    __syncthreads();

    // phase A: inverse DFT into registers
    float gre[12], gim[12];
    #pragma unroll
    for (int k = 0; k < 12; k++) {
        int o = tid + k*256;
        int c = o >> 5, m = o & 31;
        float re = 0.f, im = 0.f;
        #pragma unroll 8
        for (int u = 0; u < 32; u++) {
            float2 y = y_sh[c*32 + u];
            int idx = (u*m) & 31;
            float cw = twc[idx], sw = tws[idx];
            re += y.x*cw - y.y*sw;      // (y)(cos + i sin)
            im += y.x*sw + y.y*cw;
        }
        gre[k] = re * (1.0f/1024.0f);
        gim[k] = im * (1.0f/1024.0f);
    }
    __syncthreads();
    #pragma unroll
    for (int k = 0; k < 12; k++)
        y_sh[tid + k*256] = make_float2(gre[k], gim[k]);
    __syncthreads();

    // phase B: real part of A-mix + LN stats
    float v[8];
    float sum = 0.f, sq = 0.f;
    #pragma unroll
    for (int k = 0; k < 8; k++) {
        int o = tid + k*256;            // o = e*32 + m
        int e = o >> 5, m = o & 31;
        float acc = g_cE[e];
        #pragma unroll 16
        for (int c = 0; c < CC; c++) {
            float2 A = g_A[e*CC + c];
            float2 g = y_sh[c*32 + m];
            acc += A.x*g.x - A.y*g.y;
        }
        v[k] = acc; sum += acc; sq += acc*acc;
    }
    #pragma unroll
    for (int off = 16; off; off >>= 1) {
        sum += __shfl_xor_sync(0xffffffffu, sum, off);
        sq  += __shfl_xor_sync(0xffffffffu, sq , off);
    }
    if ((tid & 31) == 0) { red[tid>>5] = sum; red[8 + (tid>>5)] = sq; }
    __syncthreads();
    if (tid == 0) {
        float s = 0.f, q = 0.f;
        for (int w = 0; w < 8; w++) { s += red[w]; q += red[8+w]; }
        float mu  = s * (1.0f/2048.0f);
        float var = q * (1.0f/2048.0f) - mu*mu;
        red[0] = mu;
        red[1] = rsqrtf(var + 1e-5f);
    }
    __syncthreads();
    float mu = red[0], rstd = red[1];
    #pragma unroll
    for (int k = 0; k < 8; k++)
        g_vhat[bl*2048 + tid + k*256] = (v[k] - mu) * rstd;
}

// ---------------------------------------------------------------------------
// K5: epilogue  out[b,l,e,p,q] = vhat[b,l,e,(p+q)%32]*ln_w + ln_b + x
// One block per (b,l,e). vhat row staged in shared (permutation reads).
// ---------------------------------------------------------------------------
__global__ __launch_bounds__(256) void k5_final(const float* __restrict__ x,
                                                const float* __restrict__ ln_w,
                                                const float* __restrict__ ln_b,
                                                float* __restrict__ out)
{
    __shared__ float vh[32];
    int blk = blockIdx.x;                 // bl*64 + e
    int e   = blk & 63;
    int tid = threadIdx.x;
    if (tid < 32) vh[tid] = g_vhat[blk*32 + tid];
    __syncthreads();
    int q  = tid & 31;
    int p0 = tid >> 5;
    size_t xbase = (size_t)blk * 1024;
    int    lbase = e * 1024;
    #pragma unroll
    for (int k = 0; k < 4; k++) {
        int p = p0 + k*8;
        int m = (p + q) & 31;
        int off = p*32 + q;
        out[xbase + off] = vh[m]*ln_w[lbase + off] + ln_b[lbase + off] + x[xbase + off];
    }
}

// ---------------------------------------------------------------------------
extern "C" void kernel_launch(void* const* d_in, const int* in_sizes, int n_in,
                              void* d_out, int out_size)
{
    const float* x          = (const float*)d_in[0];
    const float* mask       = (const float*)d_in[1];
    const float* params_log = (const float*)d_in[2];
    const float* Wb_r  = (const float*)d_in[3],  *Wb_i  = (const float*)d_in[4];
    const float* bb_r  = (const float*)d_in[5],  *bb_i  = (const float*)d_in[6];
    const float* Wp1_r = (const float*)d_in[7],  *Wp1_i = (const float*)d_in[8];
    const float* bp1_r = (const float*)d_in[9],  *bp1_i = (const float*)d_in[10];
    const float* Wp2_r = (const float*)d_in[11], *Wp2_i = (const float*)d_in[12];
    const float* bp2_r = (const float*)d_in[13], *bp2_i = (const float*)d_in[14];
    const float* Wc_r  = (const float*)d_in[15], *Wc_i  = (const float*)d_in[16];
    const float* bc_r  = (const float*)d_in[17];   // bc_i dropped by .real
    const float* ln_w  = (const float*)d_in[19], *ln_b = (const float*)d_in[20];
    float* out = (float*)d_out;

    k0_precomp<<<CC + EE + 1, 96>>>(Wb_r, Wb_i, bb_r, bb_i,
                                    Wp1_r, Wp1_i, Wp2_r, Wp2_i,
                                    Wc_r, Wc_i, bp2_r, bp2_i, bc_r, params_log);
    k1_adiag  <<<1024, 256>>>(x);
    k2_mix_dft<<<BB*LL, 256>>>(bp1_r, bp1_i);
    k3_scan   <<<48, 256>>>(mask);
    k4_idft_ln<<<BB*LL, 256>>>();
    k5_final  <<<BB*LL*EE, 256>>>(x, ln_w, ln_b, out);
}

// round 2
// speedup vs baseline: 1.2517x; 1.2517x over previous
#include <cuda_runtime.h>
#include <math.h>

#define BB 4
#define LL 32
#define EE 64
#define CC 96
#define HH 32   // H == W == 32

// ---------------------------------------------------------------------------
// Device scratch
// ---------------------------------------------------------------------------
__device__ float2 g_D[BB*LL*CC*HH];     // spectral state D / y     (3 MB)
__device__ float  g_vhat[BB*LL*EE*HH];  // normalized v             (1 MB)
__device__ float2 g_M[CC*EE];           // Wp1 @ Wb   (complex)
__device__ float2 g_A[EE*CC];           // Wc  @ Wp2  (complex)
__device__ float2 g_lamb[CC*HH];        // lambda[c,u]
__device__ float  g_gam[CC*HH];         // gamma[c,u]
__device__ float2 g_bu0[CC];            // 1024 * (Wp1 @ bb)  (u==0 term)
__device__ float  g_cE[EE];             // Re(Wc @ bp2) + bc_r

// ---------------------------------------------------------------------------
// K0: fold parameters (tiny)
// ---------------------------------------------------------------------------
__global__ void k0_precomp(const float* __restrict__ Wb_r, const float* __restrict__ Wb_i,
                           const float* __restrict__ bb_r, const float* __restrict__ bb_i,
                           const float* __restrict__ Wp1_r, const float* __restrict__ Wp1_i,
                           const float* __restrict__ Wp2_r, const float* __restrict__ Wp2_i,
                           const float* __restrict__ Wc_r,  const float* __restrict__ Wc_i,
                           const float* __restrict__ bp2_r, const float* __restrict__ bp2_i,
                           const float* __restrict__ bc_r,
                           const float* __restrict__ params_log)
{
    int blk = blockIdx.x, tid = threadIdx.x;
    if (blk < CC) {
        int c = blk;
        if (tid < EE) {  // M = Wp1 @ Wb  (row c)
            float re = 0.f, im = 0.f;
            #pragma unroll 8
            for (int k = 0; k < CC; k++) {
                float ar = Wp1_r[c*CC+k], ai = Wp1_i[c*CC+k];
                float br = Wb_r[k*EE+tid], bi = Wb_i[k*EE+tid];
                re += ar*br - ai*bi;
                im += ar*bi + ai*br;
            }
            g_M[c*EE+tid] = make_float2(re, im);
        }
        if (tid < HH) {  // lambda, gamma
            float nu = expf(params_log[c*HH + tid]);
            float th = expf(params_log[(CC + c)*HH + tid]);
            float ga = expf(params_log[(2*CC + c)*HH + tid]);
            float r  = expf(-nu);
            float sn, cs;
            sincosf(th, &sn, &cs);
            g_lamb[c*HH+tid] = make_float2(r*cs, r*sn);
            g_gam [c*HH+tid] = ga;
        }
        if (tid == 0) {  // 1024 * (Wp1 @ bb)[c]
            float re = 0.f, im = 0.f;
            for (int k = 0; k < CC; k++) {
                float ar = Wp1_r[c*CC+k], ai = Wp1_i[c*CC+k];
                re += ar*bb_r[k] - ai*bb_i[k];
                im += ar*bb_i[k] + ai*bb_r[k];
            }
            g_bu0[c] = make_float2(1024.f*re, 1024.f*im);
        }
    } else {
        int e = blk - CC;
        if (tid < CC) {  // A = Wc @ Wp2  (row e)
            float re = 0.f, im = 0.f;
            #pragma unroll 8
            for (int k = 0; k < CC; k++) {
                float ar = Wc_r[e*CC+k], ai = Wc_i[e*CC+k];
                float br = Wp2_r[k*CC+tid], bi = Wp2_i[k*CC+tid];
                re += ar*br - ai*bi;
                im += ar*bi + ai*br;
            }
            g_A[e*CC+tid] = make_float2(re, im);
        }
        if (tid == 0) {  // constE[e] = Re(Wc@bp2)[e] + bc_r[e]
            float acc = bc_r[e];
            for (int c = 0; c < CC; c++)
                acc += Wc_r[e*CC+c]*bp2_r[c] - Wc_i[e*CC+c]*bp2_i[c];
            g_cE[e] = acc;
        }
    }
}

// ---------------------------------------------------------------------------
// K2: one block per (b,l). Fuses:
//   s[e,m]  = antidiagonal sums of x[b,l,e,:,:]
//   t[c,m]  = sum_e M[c,e]*s[e,m]
//   T[c,u]  = DFT32(t[c,:])[u]     via rotation recurrence (no twiddle LDS)
//   D[c,u]  = gamma[c,u]*(T + bp1[c] + (u==0)*1024*(Wp1@bb)[c])
// Warp w owns c = w + 8*j (uniform per warp -> matrix reads are LDS broadcast)
// ---------------------------------------------------------------------------
__global__ __launch_bounds__(256) void k2_mix_dft(const float* __restrict__ x,
                                                  const float* __restrict__ bp1_r,
                                                  const float* __restrict__ bp1_i)
{
    __shared__ float  s_sh[EE*32];      //  8 KB
    __shared__ float2 Mt  [CC*32];      // 24 KB  (M chunk, then t)
    int bl = blockIdx.x, tid = threadIdx.x;
    int w  = tid >> 5, lane = tid & 31;

    // --- antidiagonal sums: warp w handles e = w*8 .. w*8+7 ---
    {
        const float* xp = x + ((size_t)bl*EE + w*8) * 1024;
        #pragma unroll
        for (int j = 0; j < 8; j++) {
            float acc = 0.f;
            #pragma unroll
            for (int p = 0; p < 32; p++)
                acc += xp[j*1024 + p*32 + ((lane - p) & 31)];
            s_sh[(w*8 + j)*32 + lane] = acc;
        }
    }
    __syncthreads();

    // --- channel mix, e in two chunks of 32 with M staged in shared ---
    float tre[12], tim[12];
    #pragma unroll
    for (int j = 0; j < 12; j++) { tre[j] = 0.f; tim[j] = 0.f; }

    #pragma unroll
    for (int half = 0; half < 2; half++) {
        for (int i = tid; i < CC*32; i += 256) {
            int c = i >> 5, e = i & 31;
            Mt[i] = g_M[c*EE + half*32 + e];
        }
        __syncthreads();
        #pragma unroll 4
        for (int e = 0; e < 32; e++) {
            float sv = s_sh[(half*32 + e)*32 + lane];
            #pragma unroll
            for (int j = 0; j < 12; j++) {
                float2 Mv = Mt[(w + 8*j)*32 + e];   // broadcast
                tre[j] += Mv.x * sv;
                tim[j] += Mv.y * sv;
            }
        }
        __syncthreads();
    }

    // t -> shared
    #pragma unroll
    for (int j = 0; j < 12; j++)
        Mt[(w + 8*j)*32 + lane] = make_float2(tre[j], tim[j]);
    __syncthreads();

    // --- DFT32 over m, u = lane, rotation step e^{-i 2pi u/32} ---
    float cu, su;
    sincospif((float)lane / 16.0f, &su, &cu);
    #pragma unroll
    for (int j = 0; j < 12; j++) {
        int c = w + 8*j;
        float re = 0.f, im = 0.f;
        float cw = 1.f, swp = 0.f;   // (cw, swp) = (cos, sin)(2pi*u*m/32)
        #pragma unroll 8
        for (int m = 0; m < 32; m++) {
            float2 t = Mt[c*32 + m];                 // broadcast
            re += t.x*cw + t.y*swp;
            im += t.y*cw - t.x*swp;
            float ncw = cw*cu - swp*su;
            swp = swp*cu + cw*su;
            cw  = ncw;
        }
        re += bp1_r[c]; im += bp1_i[c];
        if (lane == 0) { float2 b = g_bu0[c]; re += b.x; im += b.y; }
        float ga = g_gam[c*32 + lane];
        g_D[(bl*CC + c)*32 + lane] = make_float2(re*ga, im*ga);
    }
}

// ---------------------------------------------------------------------------
// K3: parallel LRU scan. Warp per (b,c,u), lane = l. Affine-map warp scan.
//   y[l] = d[l] + a[l]*y[l-1],  a[l] = lamb * mask[l-1]  (a[0]=0)
// ---------------------------------------------------------------------------
__global__ __launch_bounds__(256) void k3_scan(const float* __restrict__ mask)
{
    int w    = threadIdx.x >> 5;
    int lane = threadIdx.x & 31;               // = l
    int bc   = blockIdx.x >> 2;                // (b,c) pair
    int u    = ((blockIdx.x & 3) << 3) + w;
    int b    = bc / CC, c = bc % CC;

    int idx  = ((b*LL + lane)*CC + c)*HH + u;
    float2 d = g_D[idx];
    float2 lam = g_lamb[c*HH + u];
    float mv = (lane == 0) ? 0.f : __ldg(&mask[b*LL + lane - 1]);
    float ar = lam.x * mv, ai = lam.y * mv;
    float dr = d.x, di = d.y;

    #pragma unroll
    for (int off = 1; off < 32; off <<= 1) {
        float par = __shfl_up_sync(0xffffffffu, ar, off);
        float pai = __shfl_up_sync(0xffffffffu, ai, off);
        float pdr = __shfl_up_sync(0xffffffffu, dr, off);
        float pdi = __shfl_up_sync(0xffffffffu, di, off);
        if (lane >= off) {
            float ndr = dr + ar*pdr - ai*pdi;
            float ndi = di + ar*pdi + ai*pdr;
            float nar = ar*par - ai*pai;
            float nai = ar*pai + ai*par;
            dr = ndr; di = ndi; ar = nar; ai = nai;
        }
    }
    g_D[idx] = make_float2(dr, di);
}

// ---------------------------------------------------------------------------
// K4: one block per (b,l).
//   g[c,m] = (1/1024) sum_u y[c,u] e^{+i 2pi um/32}   (rotation recurrence)
//   v[e,m] = Re(sum_c A[e,c] g[c,m]) + constE[e]
//   LN stats over 2048 values, vhat = (v - mu)*rstd
// ---------------------------------------------------------------------------
__global__ __launch_bounds__(256) void k4_idft_ln()
{
    __shared__ float2 y_sh[CC*32];      // 24 KB (y, then g)
    __shared__ float2 A_sh[EE*32];      // 16 KB (A chunk)
    __shared__ float  red[18];
    int bl = blockIdx.x, tid = threadIdx.x;
    int w  = tid >> 5, lane = tid & 31;

    for (int i = tid; i < CC*32; i += 256) y_sh[i] = g_D[bl*CC*32 + i];
    __syncthreads();

    // --- inverse DFT: thread owns (c = w+8j, m = lane) ---
    float cm, sm;
    sincospif((float)lane / 16.0f, &sm, &cm);
    float gre[12], gim[12];
    #pragma unroll
    for (int j = 0; j < 12; j++) {
        int c = w + 8*j;
        float re = 0.f, im = 0.f;
        float cw = 1.f, swp = 0.f;   // (cos, sin)(2pi*u*m/32)
        #pragma unroll 8
        for (int u = 0; u < 32; u++) {
            float2 y = y_sh[c*32 + u];               // broadcast
            re += y.x*cw - y.y*swp;
            im += y.x*swp + y.y*cw;
            float ncw = cw*cm - swp*sm;
            swp = swp*cm + cw*sm;
            cw  = ncw;
        }
        gre[j] = re * (1.0f/1024.0f);
        gim[j] = im * (1.0f/1024.0f);
    }
    __syncthreads();
    #pragma unroll
    for (int j = 0; j < 12; j++)
        y_sh[(w + 8*j)*32 + lane] = make_float2(gre[j], gim[j]);
    __syncthreads();

    // --- A-mix (real part): thread owns (e = w*8+j, m = lane), c in 3 chunks ---
    float v[8];
    #pragma unroll
    for (int j = 0; j < 8; j++) v[j] = g_cE[w*8 + j];

    #pragma unroll
    for (int ch = 0; ch < 3; ch++) {
        for (int i = tid; i < EE*32; i += 256) {
            int e = i >> 5, cc = i & 31;
            A_sh[i] = g_A[e*CC + ch*32 + cc];
        }
        __syncthreads();
        #pragma unroll 4
        for (int cc = 0; cc < 32; cc++) {
            float2 g = y_sh[(ch*32 + cc)*32 + lane];
            #pragma unroll
            for (int j = 0; j < 8; j++) {
                float2 A = A_sh[(w*8 + j)*32 + cc];  // broadcast
                v[j] += A.x*g.x - A.y*g.y;
            }
        }
        __syncthreads();
    }

    // --- LN stats over the 2048 v's ---
    float sum = 0.f, sq = 0.f;
    #pragma unroll
    for (int j = 0; j < 8; j++) { sum += v[j]; sq += v[j]*v[j]; }
    #pragma unroll
    for (int off = 16; off; off >>= 1) {
        sum += __shfl_xor_sync(0xffffffffu, sum, off);
        sq  += __shfl_xor_sync(0xffffffffu, sq , off);
    }
    if (lane == 0) { red[w] = sum; red[8 + w] = sq; }
    __syncthreads();
    if (tid == 0) {
        float s = 0.f, q = 0.f;
        #pragma unroll
        for (int i = 0; i < 8; i++) { s += red[i]; q += red[8+i]; }
        float mu  = s * (1.0f/2048.0f);
        float var = q * (1.0f/2048.0f) - mu*mu;
        red[16] = mu;
        red[17] = rsqrtf(var + 1e-5f);
    }
    __syncthreads();
    float mu = red[16], rstd = red[17];
    #pragma unroll
    for (int j = 0; j < 8; j++)
        g_vhat[bl*2048 + (w*8 + j)*32 + lane] = (v[j] - mu) * rstd;
}

// ---------------------------------------------------------------------------
// K5: epilogue, float4-vectorized. Block handles 4 e-tiles of one (b,l).
//   out = vhat[(p+q)%32]*ln_w + ln_b + x
// ---------------------------------------------------------------------------
__global__ __launch_bounds__(256) void k5_final(const float* __restrict__ x,
                                                const float* __restrict__ ln_w,
                                                const float* __restrict__ ln_b,
                                                float* __restrict__ out)
{
    __shared__ float vh[128];
    int blk = blockIdx.x;               // bl*16 + eg
    int bl  = blk >> 4, eg = blk & 15;
    int tid = threadIdx.x;
    if (tid < 128) vh[tid] = g_vhat[bl*2048 + eg*128 + tid];
    __syncthreads();

    const float4* x4  = (const float4*)x;
    const float4* lw4 = (const float4*)ln_w;
    const float4* lb4 = (const float4*)ln_b;
    float4*       o4  = (float4*)out;
    size_t base4 = ((size_t)bl*EE + eg*4) * 256;

    #pragma unroll
    for (int t = 0; t < 4; t++) {
        int idx4 = t*256 + tid;              // 0..1023
        int el   = idx4 >> 8;                // local e (0..3)
        int r    = idx4 & 255;               // float4 index within tile
        int p    = r >> 3;
        int q0   = (r & 7) * 4;
        int e    = eg*4 + el;

        float4 xv = x4 [base4 + idx4];
        float4 wv = lw4[(size_t)e*256 + r];
        float4 bv = lb4[(size_t)e*256 + r];
        float4 ov;
        ov.x = vh[el*32 + ((p + q0    ) & 31)]*wv.x + bv.x + xv.x;
        ov.y = vh[el*32 + ((p + q0 + 1) & 31)]*wv.y + bv.y + xv.y;
        ov.z = vh[el*32 + ((p + q0 + 2) & 31)]*wv.z + bv.z + xv.z;
        ov.w = vh[el*32 + ((p + q0 + 3) & 31)]*wv.w + bv.w + xv.w;
        o4[base4 + idx4] = ov;
    }
}

// ---------------------------------------------------------------------------
extern "C" void kernel_launch(void* const* d_in, const int* in_sizes, int n_in,
                              void* d_out, int out_size)
{
    const float* x          = (const float*)d_in[0];
    const float* mask       = (const float*)d_in[1];
    const float* params_log = (const float*)d_in[2];
    const float* Wb_r  = (const float*)d_in[3],  *Wb_i  = (const float*)d_in[4];
    const float* bb_r  = (const float*)d_in[5],  *bb_i  = (const float*)d_in[6];
    const float* Wp1_r = (const float*)d_in[7],  *Wp1_i = (const float*)d_in[8];
    const float* bp1_r = (const float*)d_in[9],  *bp1_i = (const float*)d_in[10];
    const float* Wp2_r = (const float*)d_in[11], *Wp2_i = (const float*)d_in[12];
    const float* bp2_r = (const float*)d_in[13], *bp2_i = (const float*)d_in[14];
    const float* Wc_r  = (const float*)d_in[15], *Wc_i  = (const float*)d_in[16];
    const float* bc_r  = (const float*)d_in[17];   // bc_i dropped by .real
    const float* ln_w  = (const float*)d_in[19], *ln_b = (const float*)d_in[20];
    float* out = (float*)d_out;

    k0_precomp<<<CC + EE, 96>>>(Wb_r, Wb_i, bb_r, bb_i,
                                Wp1_r, Wp1_i, Wp2_r, Wp2_i,
                                Wc_r, Wc_i, bp2_r, bp2_i, bc_r, params_log);
    k2_mix_dft<<<BB*LL, 256>>>(x, bp1_r, bp1_i);
    k3_scan   <<<BB*CC*4, 256>>>(mask);
    k4_idft_ln<<<BB*LL, 256>>>();
    k5_final  <<<BB*LL*16, 256>>>(x, ln_w, ln_b, out);
}

// round 4
// speedup vs baseline: 1.5563x; 1.2434x over previous
#include <cuda_runtime.h>
#include <math.h>

#define BB 4
#define LL 32
#define EE 64
#define CC 96
#define HH 32   // H == W == 32

// ---------------------------------------------------------------------------
// Device scratch
// ---------------------------------------------------------------------------
__device__ float  g_s[BB*LL*EE*HH];     // antidiagonal sums        (1 MB)
__device__ float2 g_D[BB*LL*CC*HH];     // spectral state D / y     (3 MB)
__device__ float  g_vhat[BB*LL*EE*HH];  // normalized v             (1 MB)
__device__ float2 g_M[CC*EE];           // Wp1 @ Wb   (complex)
__device__ float2 g_A[EE*CC];           // Wc  @ Wp2  (complex)
__device__ float2 g_lamb[CC*HH];        // lambda[c,u]
__device__ float  g_gam[CC*HH];         // gamma[c,u]
__device__ float2 g_bu0[CC];            // 1024 * (Wp1 @ bb)  (u==0 term)
__device__ float  g_cE[EE];             // Re(Wc @ bp2) + bc_r

// ---------------------------------------------------------------------------
// K0: fold parameters (tiny)
// ---------------------------------------------------------------------------
__global__ void k0_precomp(const float* __restrict__ Wb_r, const float* __restrict__ Wb_i,
                           const float* __restrict__ bb_r, const float* __restrict__ bb_i,
                           const float* __restrict__ Wp1_r, const float* __restrict__ Wp1_i,
                           const float* __restrict__ Wp2_r, const float* __restrict__ Wp2_i,
                           const float* __restrict__ Wc_r,  const float* __restrict__ Wc_i,
                           const float* __restrict__ bp2_r, const float* __restrict__ bp2_i,
                           const float* __restrict__ bc_r,
                           const float* __restrict__ params_log)
{
    int blk = blockIdx.x, tid = threadIdx.x;
    if (blk < CC) {
        int c = blk;
        if (tid < EE) {  // M = Wp1 @ Wb  (row c)
            float re = 0.f, im = 0.f;
            #pragma unroll 8
            for (int k = 0; k < CC; k++) {
                float ar = Wp1_r[c*CC+k], ai = Wp1_i[c*CC+k];
                float br = Wb_r[k*EE+tid], bi = Wb_i[k*EE+tid];
                re += ar*br - ai*bi;
                im += ar*bi + ai*br;
            }
            g_M[c*EE+tid] = make_float2(re, im);
        }
        if (tid < HH) {  // lambda, gamma
            float nu = expf(params_log[c*HH + tid]);
            float th = expf(params_log[(CC + c)*HH + tid]);
            float ga = expf(params_log[(2*CC + c)*HH + tid]);
            float r  = expf(-nu);
            float sn, cs;
            sincosf(th, &sn, &cs);
            g_lamb[c*HH+tid] = make_float2(r*cs, r*sn);
            g_gam [c*HH+tid] = ga;
        }
        if (tid == 0) {  // 1024 * (Wp1 @ bb)[c]
            float re = 0.f, im = 0.f;
            for (int k = 0; k < CC; k++) {
                float ar = Wp1_r[c*CC+k], ai = Wp1_i[c*CC+k];
                re += ar*bb_r[k] - ai*bb_i[k];
                im += ar*bb_i[k] + ai*bb_r[k];
            }
            g_bu0[c] = make_float2(1024.f*re, 1024.f*im);
        }
    } else {
        int e = blk - CC;
        if (tid < CC) {  // A = Wc @ Wp2  (row e)
            float re = 0.f, im = 0.f;
            #pragma unroll 8
            for (int k = 0; k < CC; k++) {
                float ar = Wc_r[e*CC+k], ai = Wc_i[e*CC+k];
                float br = Wp2_r[k*CC+tid], bi = Wp2_i[k*CC+tid];
                re += ar*br - ai*bi;
                im += ar*bi + ai*br;
            }
            g_A[e*CC+tid] = make_float2(re, im);
        }
        if (tid == 0) {  // constE[e] = Re(Wc@bp2)[e] + bc_r[e]
            float acc = bc_r[e];
            for (int c = 0; c < CC; c++)
                acc += Wc_r[e*CC+c]*bp2_r[c] - Wc_i[e*CC+c]*bp2_i[c];
            g_cE[e] = acc;
        }
    }
}

// ---------------------------------------------------------------------------
// K1: antidiagonal sums  s[bl,e,m] = sum_{(p+q)%32==m} x[bl,e,p,q]
// Warp per (bl,e) tile; lane m reads rotated rows (coalesced line-wise).
// Pure x-read pass at full chip bandwidth.
// ---------------------------------------------------------------------------
__global__ __launch_bounds__(256) void k1_adiag(const float* __restrict__ x)
{
    int w    = blockIdx.x * 8 + (threadIdx.x >> 5);   // 0..8191
    int lane = threadIdx.x & 31;
    const float* xp = x + (size_t)w * 1024;
    float acc = 0.f;
    #pragma unroll
    for (int p = 0; p < 32; p++)
        acc += xp[p*32 + ((lane - p) & 31)];
    g_s[w*32 + lane] = acc;
}

// ---------------------------------------------------------------------------
// K2: mix + DFT. Grid = 128 bl x 2 c-halves (256 blocks, 256 threads).
//   t[c,m] = sum_e M[c,e]*s[e,m]
//   T[c,u] = DFT32(t[c,:])[u]
//   D[c,u] = gamma*(T + bp1 + (u==0)*bu0)
// Warp w owns c_loc = w + 8j (j<6). Rotation hoisted over j.
// ---------------------------------------------------------------------------
__global__ __launch_bounds__(256) void k2_mix_dft(const float* __restrict__ bp1_r,
                                                  const float* __restrict__ bp1_i)
{
    __shared__ float  s_sh[EE*32];      //  8 KB
    __shared__ float2 Mt  [48*32];      // 12 KB (M chunk, then t)
    int bl = blockIdx.x >> 1, cs = blockIdx.x & 1;
    int cbase = cs * 48;
    int tid = threadIdx.x;
    int w  = tid >> 5, lane = tid & 31;

    for (int i = tid; i < EE*32; i += 256) s_sh[i] = g_s[bl*EE*32 + i];

    float tre[6], tim[6];
    #pragma unroll
    for (int j = 0; j < 6; j++) { tre[j] = 0.f; tim[j] = 0.f; }

    #pragma unroll
    for (int half = 0; half < 2; half++) {
        __syncthreads();
        for (int i = tid; i < 48*32; i += 256) {
            int cl = i >> 5, e = i & 31;
            Mt[i] = g_M[(cbase + cl)*EE + half*32 + e];
        }
        __syncthreads();
        #pragma unroll 4
        for (int e = 0; e < 32; e++) {
            float sv = s_sh[(half*32 + e)*32 + lane];
            #pragma unroll
            for (int j = 0; j < 6; j++) {
                float2 Mv = Mt[(w + 8*j)*32 + e];   // broadcast
                tre[j] += Mv.x * sv;
                tim[j] += Mv.y * sv;
            }
        }
    }
    __syncthreads();

    // t -> shared
    #pragma unroll
    for (int j = 0; j < 6; j++)
        Mt[(w + 8*j)*32 + lane] = make_float2(tre[j], tim[j]);
    __syncthreads();

    // --- DFT32: u = lane, rotation step shared across the 6 c's ---
    float cu, su;
    sincospif((float)lane / 16.0f, &su, &cu);
    float re[6], im[6];
    #pragma unroll
    for (int j = 0; j < 6; j++) { re[j] = 0.f; im[j] = 0.f; }
    float cw = 1.f, swp = 0.f;   // (cos, sin)(2pi*u*m/32)
    #pragma unroll 8
    for (int m = 0; m < 32; m++) {
        #pragma unroll
        for (int j = 0; j < 6; j++) {
            float2 t = Mt[(w + 8*j)*32 + m];         // broadcast
            re[j] += t.x*cw + t.y*swp;
            im[j] += t.y*cw - t.x*swp;
        }
        float ncw = cw*cu - swp*su;
        swp = swp*cu + cw*su;
        cw  = ncw;
    }
    #pragma unroll
    for (int j = 0; j < 6; j++) {
        int c = cbase + w + 8*j;
        float rr = re[j] + bp1_r[c];
        float ii = im[j] + bp1_i[c];
        if (lane == 0) { float2 b = g_bu0[c]; rr += b.x; ii += b.y; }
        float ga = g_gam[c*32 + lane];
        g_D[(bl*CC + c)*32 + lane] = make_float2(rr*ga, ii*ga);
    }
}

// ---------------------------------------------------------------------------
// K3: parallel LRU scan. Warp per (b,c,u), lane = l. Affine-map warp scan.
// ---------------------------------------------------------------------------
__global__ __launch_bounds__(256) void k3_scan(const float* __restrict__ mask)
{
    int w    = threadIdx.x >> 5;
    int lane = threadIdx.x & 31;               // = l
    int bc   = blockIdx.x >> 2;                // (b,c) pair
    int u    = ((blockIdx.x & 3) << 3) + w;
    int b    = bc / CC, c = bc % CC;

    int idx  = ((b*LL + lane)*CC + c)*HH + u;
    float2 d = g_D[idx];
    float2 lam = g_lamb[c*HH + u];
    float mv = (lane == 0) ? 0.f : __ldg(&mask[b*LL + lane - 1]);
    float ar = lam.x * mv, ai = lam.y * mv;
    float dr = d.x, di = d.y;

    #pragma unroll
    for (int off = 1; off < 32; off <<= 1) {
        float par = __shfl_up_sync(0xffffffffu, ar, off);
        float pai = __shfl_up_sync(0xffffffffu, ai, off);
        float pdr = __shfl_up_sync(0xffffffffu, dr, off);
        float pdi = __shfl_up_sync(0xffffffffu, di, off);
        if (lane >= off) {
            float ndr = dr + ar*pdr - ai*pdi;
            float ndi = di + ar*pdi + ai*pdr;
            float nar = ar*par - ai*pai;
            float nai = ar*pai + ai*par;
            dr = ndr; di = ndi; ar = nar; ai = nai;
        }
    }
    g_D[idx] = make_float2(dr, di);
}

// ---------------------------------------------------------------------------
// K4: one block of 512 per (b,l).
//   g[c,m] = (1/1024) sum_u y[c,u] e^{+i 2pi um/32}   (rotation hoisted)
//   v[e,m] = Re(sum_c A[e,c] g[c,m]) + constE[e]
//   LN stats over 2048 values, vhat = (v - mu)*rstd
// 16 warps: phase A c = w + 16j (j<6), phase B e = w*4+j (j<4), m = lane.
// ---------------------------------------------------------------------------
__global__ __launch_bounds__(512) void k4_idft_ln()
{
    __shared__ float2 y_sh[CC*32];      // 24 KB (y, then g)
    __shared__ float2 A_sh[EE*32];      // 16 KB (A chunk)
    __shared__ float  red[34];
    int bl = blockIdx.x, tid = threadIdx.x;
    int w  = tid >> 5, lane = tid & 31;

    for (int i = tid; i < CC*32; i += 512) y_sh[i] = g_D[bl*CC*32 + i];
    __syncthreads();

    // --- inverse DFT: thread owns (c = w+16j, m = lane) ---
    float cm, sm;
    sincospif((float)lane / 16.0f, &sm, &cm);
    float gre[6], gim[6];
    #pragma unroll
    for (int j = 0; j < 6; j++) { gre[j] = 0.f; gim[j] = 0.f; }
    float cw = 1.f, swp = 0.f;   // (cos, sin)(2pi*u*m/32)
    #pragma unroll 8
    for (int u = 0; u < 32; u++) {
        #pragma unroll
        for (int j = 0; j < 6; j++) {
            float2 y = y_sh[(w + 16*j)*32 + u];      // broadcast
            gre[j] += y.x*cw - y.y*swp;
            gim[j] += y.x*swp + y.y*cw;
        }
        float ncw = cw*cm - swp*sm;
        swp = swp*cm + cw*sm;
        cw  = ncw;
    }
    __syncthreads();
    #pragma unroll
    for (int j = 0; j < 6; j++)
        y_sh[(w + 16*j)*32 + lane] =
            make_float2(gre[j] * (1.0f/1024.0f), gim[j] * (1.0f/1024.0f));
    __syncthreads();

    // --- A-mix (real part): thread owns (e = w*4+j, m = lane), c in 3 chunks ---
    float v[4];
    #pragma unroll
    for (int j = 0; j < 4; j++) v[j] = g_cE[w*4 + j];

    #pragma unroll
    for (int ch = 0; ch < 3; ch++) {
        for (int i = tid; i < EE*32; i += 512) {
            int e = i >> 5, cc = i & 31;
            A_sh[i] = g_A[e*CC + ch*32 + cc];
        }
        __syncthreads();
        #pragma unroll 4
        for (int cc = 0; cc < 32; cc++) {
            float2 g = y_sh[(ch*32 + cc)*32 + lane];
            #pragma unroll
            for (int j = 0; j < 4; j++) {
                float2 A = A_sh[(w*4 + j)*32 + cc];  // broadcast
                v[j] += A.x*g.x - A.y*g.y;
            }
        }
        __syncthreads();
    }

    // --- LN stats over the 2048 v's ---
    float sum = 0.f, sq = 0.f;
    #pragma unroll
    for (int j = 0; j < 4; j++) { sum += v[j]; sq += v[j]*v[j]; }
    #pragma unroll
    for (int off = 16; off; off >>= 1) {
        sum += __shfl_xor_sync(0xffffffffu, sum, off);
        sq  += __shfl_xor_sync(0xffffffffu, sq , off);
    }
    if (lane == 0) { red[w] = sum; red[16 + w] = sq; }
    __syncthreads();
    if (tid == 0) {
        float s = 0.f, q = 0.f;
        #pragma unroll
        for (int i = 0; i < 16; i++) { s += red[i]; q += red[16+i]; }
        float mu  = s * (1.0f/2048.0f);
        float var = q * (1.0f/2048.0f) - mu*mu;
        red[32] = mu;
        red[33] = rsqrtf(var + 1e-5f);
    }
    __syncthreads();
    float mu = red[32], rstd = red[33];
    #pragma unroll
    for (int j = 0; j < 4; j++)
        g_vhat[bl*2048 + (w*4 + j)*32 + lane] = (v[j] - mu) * rstd;
}

// ---------------------------------------------------------------------------
// K5: epilogue, float4-vectorized. Block handles 4 e-tiles of one (b,l).
//   out = vhat[(p+q)%32]*ln_w + ln_b + x
// ---------------------------------------------------------------------------
__global__ __launch_bounds__(256) void k5_final(const float* __restrict__ x,
                                                const float* __restrict__ ln_w,
                                                const float* __restrict__ ln_b,
                                                float* __restrict__ out)
{
    __shared__ float vh[128];
    int blk = blockIdx.x;               // bl*16 + eg
    int bl  = blk >> 4, eg = blk & 15;
    int tid = threadIdx.x;
    if (tid < 128) vh[tid] = g_vhat[bl*2048 + eg*128 + tid];
    __syncthreads();

    const float4* x4  = (const float4*)x;
    const float4* lw4 = (const float4*)ln_w;
    const float4* lb4 = (const float4*)ln_b;
    float4*       o4  = (float4*)out;
    size_t base4 = ((size_t)bl*EE + eg*4) * 256;

    #pragma unroll
    for (int t = 0; t < 4; t++) {
        int idx4 = t*256 + tid;              // 0..1023
        int el   = idx4 >> 8;                // local e (0..3)
        int r    = idx4 & 255;               // float4 index within tile
        int p    = r >> 3;
        int q0   = (r & 7) * 4;
        int e    = eg*4 + el;

        float4 xv = x4 [base4 + idx4];
        float4 wv = lw4[(size_t)e*256 + r];
        float4 bv = lb4[(size_t)e*256 + r];
        float4 ov;
        ov.x = vh[el*32 + ((p + q0    ) & 31)]*wv.x + bv.x + xv.x;
        ov.y = vh[el*32 + ((p + q0 + 1) & 31)]*wv.y + bv.y + xv.y;
        ov.z = vh[el*32 + ((p + q0 + 2) & 31)]*wv.z + bv.z + xv.z;
        ov.w = vh[el*32 + ((p + q0 + 3) & 31)]*wv.w + bv.w + xv.w;
        o4[base4 + idx4] = ov;
    }
}

// ---------------------------------------------------------------------------
extern "C" void kernel_launch(void* const* d_in, const int* in_sizes, int n_in,
                              void* d_out, int out_size)
{
    const float* x          = (const float*)d_in[0];
    const float* mask       = (const float*)d_in[1];
    const float* params_log = (const float*)d_in[2];
    const float* Wb_r  = (const float*)d_in[3],  *Wb_i  = (const float*)d_in[4];
    const float* bb_r  = (const float*)d_in[5],  *bb_i  = (const float*)d_in[6];
    const float* Wp1_r = (const float*)d_in[7],  *Wp1_i = (const float*)d_in[8];
    const float* bp1_r = (const float*)d_in[9],  *bp1_i = (const float*)d_in[10];
    const float* Wp2_r = (const float*)d_in[11], *Wp2_i = (const float*)d_in[12];
    const float* bp2_r = (const float*)d_in[13], *bp2_i = (const float*)d_in[14];
    const float* Wc_r  = (const float*)d_in[15], *Wc_i  = (const float*)d_in[16];
    const float* bc_r  = (const float*)d_in[17];   // bc_i dropped by .real
    const float* ln_w  = (const float*)d_in[19], *ln_b = (const float*)d_in[20];
    float* out = (float*)d_out;

    k0_precomp<<<CC + EE, 96>>>(Wb_r, Wb_i, bb_r, bb_i,
                                Wp1_r, Wp1_i, Wp2_r, Wp2_i,
                                Wc_r, Wc_i, bp2_r, bp2_i, bc_r, params_log);
    k1_adiag  <<<1024, 256>>>(x);
    k2_mix_dft<<<BB*LL*2, 256>>>(bp1_r, bp1_i);
    k3_scan   <<<BB*CC*4, 256>>>(mask);
    k4_idft_ln<<<BB*LL, 512>>>();
    k5_final  <<<BB*LL*16, 256>>>(x, ln_w, ln_b, out);
}

// round 7
// speedup vs baseline: 1.5745x; 1.0117x over previous
#include <cuda_runtime.h>
#include <math.h>

#define BB 4
#define LL 32
#define EE 64
#define CC 96
#define HH 32   // H == W == 32

// ---------------------------------------------------------------------------
// Device scratch
// ---------------------------------------------------------------------------
__device__ float  g_s[BB*LL*EE*HH];     // antidiagonal sums        (1 MB)
__device__ float2 g_D[BB*LL*CC*HH];     // spectral state D / y     (3 MB)
__device__ float2 g_M[CC*EE];           // Wp1 @ Wb   (complex)
__device__ float2 g_A[EE*CC];           // Wc  @ Wp2  (complex)
__device__ float2 g_lamb[CC*HH];        // lambda[c,u]  (index = c*32+u)
__device__ float  g_gam[CC*HH];         // gamma[c,u]
__device__ float2 g_bu0[CC];            // 1024 * (Wp1 @ bb)  (u==0 term)
__device__ float  g_cE[EE];             // Re(Wc @ bp2) + bc_r

// ---------------------------------------------------------------------------
// K0: fold parameters (tiny)
// ---------------------------------------------------------------------------
__global__ void k0_precomp(const float* __restrict__ Wb_r, const float* __restrict__ Wb_i,
                           const float* __restrict__ bb_r, const float* __restrict__ bb_i,
                           const float* __restrict__ Wp1_r, const float* __restrict__ Wp1_i,
                           const float* __restrict__ Wp2_r, const float* __restrict__ Wp2_i,
                           const float* __restrict__ Wc_r,  const float* __restrict__ Wc_i,
                           const float* __restrict__ bp2_r, const float* __restrict__ bp2_i,
                           const float* __restrict__ bc_r,
                           const float* __restrict__ params_log)
{
    int blk = blockIdx.x, tid = threadIdx.x;
    if (blk < CC) {
        int c = blk;
        if (tid < EE) {  // M = Wp1 @ Wb  (row c)
            float re = 0.f, im = 0.f;
            #pragma unroll 8
            for (int k = 0; k < CC; k++) {
                float ar = Wp1_r[c*CC+k], ai = Wp1_i[c*CC+k];
                float br = Wb_r[k*EE+tid], bi = Wb_i[k*EE+tid];
                re += ar*br - ai*bi;
                im += ar*bi + ai*br;
            }
            g_M[c*EE+tid] = make_float2(re, im);
        }
        if (tid < HH) {  // lambda, gamma
            float nu = expf(params_log[c*HH + tid]);
            float th = expf(params_log[(CC + c)*HH + tid]);
            float ga = expf(params_log[(2*CC + c)*HH + tid]);
            float r  = expf(-nu);
            float sn, cs;
            sincosf(th, &sn, &cs);
            g_lamb[c*HH+tid] = make_float2(r*cs, r*sn);
            g_gam [c*HH+tid] = ga;
        }
        if (tid == 0) {  // 1024 * (Wp1 @ bb)[c]
            float re = 0.f, im = 0.f;
            for (int k = 0; k < CC; k++) {
                float ar = Wp1_r[c*CC+k], ai = Wp1_i[c*CC+k];
                re += ar*bb_r[k] - ai*bb_i[k];
                im += ar*bb_i[k] + ai*bb_r[k];
            }
            g_bu0[c] = make_float2(1024.f*re, 1024.f*im);
        }
    } else {
        int e = blk - CC;
        if (tid < CC) {  // A = Wc @ Wp2  (row e)
            float re = 0.f, im = 0.f;
            #pragma unroll 8
            for (int k = 0; k < CC; k++) {
                float ar = Wc_r[e*CC+k], ai = Wc_i[e*CC+k];
                float br = Wp2_r[k*CC+tid], bi = Wp2_i[k*CC+tid];
                re += ar*br - ai*bi;
                im += ar*bi + ai*br;
            }
            g_A[e*CC+tid] = make_float2(re, im);
        }
        if (tid == 0) {  // constE[e] = Re(Wc@bp2)[e] + bc_r[e]
            float acc = bc_r[e];
            for (int c = 0; c < CC; c++)
                acc += Wc_r[e*CC+c]*bp2_r[c] - Wc_i[e*CC+c]*bp2_i[c];
            g_cE[e] = acc;
        }
    }
}

// ---------------------------------------------------------------------------
// K1: antidiagonal sums  s[bl,e,m] = sum_{(p+q)%32==m} x[bl,e,p,q]
// ---------------------------------------------------------------------------
__global__ __launch_bounds__(256) void k1_adiag(const float* __restrict__ x)
{
    int w    = blockIdx.x * 8 + (threadIdx.x >> 5);   // 0..8191
    int lane = threadIdx.x & 31;
    const float* xp = x + (size_t)w * 1024;
    float acc = 0.f;
    #pragma unroll
    for (int p = 0; p < 32; p++)
        acc += xp[p*32 + ((lane - p) & 31)];
    g_s[w*32 + lane] = acc;
}

// ---------------------------------------------------------------------------
// K2: mix + DFT. Grid = 128 bl x 2 c-halves (256 blocks, 256 threads).
// ---------------------------------------------------------------------------
__global__ __launch_bounds__(256) void k2_mix_dft(const float* __restrict__ bp1_r,
                                                  const float* __restrict__ bp1_i)
{
    __shared__ float  s_sh[EE*32];      //  8 KB
    __shared__ float2 Mt  [48*32];      // 12 KB (M chunk, then t)
    int bl = blockIdx.x >> 1, cs = blockIdx.x & 1;
    int cbase = cs * 48;
    int tid = threadIdx.x;
    int w  = tid >> 5, lane = tid & 31;

    for (int i = tid; i < EE*32; i += 256) s_sh[i] = g_s[bl*EE*32 + i];

    float tre[6], tim[6];
    #pragma unroll
    for (int j = 0; j < 6; j++) { tre[j] = 0.f; tim[j] = 0.f; }

    #pragma unroll
    for (int half = 0; half < 2; half++) {
        __syncthreads();
        for (int i = tid; i < 48*32; i += 256) {
            int cl = i >> 5, e = i & 31;
            Mt[i] = g_M[(cbase + cl)*EE + half*32 + e];
        }
        __syncthreads();
        #pragma unroll 4
        for (int e = 0; e < 32; e++) {
            float sv = s_sh[(half*32 + e)*32 + lane];
            #pragma unroll
            for (int j = 0; j < 6; j++) {
                float2 Mv = Mt[(w + 8*j)*32 + e];   // broadcast
                tre[j] += Mv.x * sv;
                tim[j] += Mv.y * sv;
            }
        }
    }
    __syncthreads();

    #pragma unroll
    for (int j = 0; j < 6; j++)
        Mt[(w + 8*j)*32 + lane] = make_float2(tre[j], tim[j]);
    __syncthreads();

    // DFT32: u = lane, rotation hoisted across the 6 c's
    float cu, su;
    sincospif((float)lane / 16.0f, &su, &cu);
    float re[6], im[6];
    #pragma unroll
    for (int j = 0; j < 6; j++) { re[j] = 0.f; im[j] = 0.f; }
    float cw = 1.f, swp = 0.f;
    #pragma unroll 8
    for (int m = 0; m < 32; m++) {
        #pragma unroll
        for (int j = 0; j < 6; j++) {
            float2 t = Mt[(w + 8*j)*32 + m];
            re[j] += t.x*cw + t.y*swp;
            im[j] += t.y*cw - t.x*swp;
        }
        float ncw = cw*cu - swp*su;
        swp = swp*cu + cw*su;
        cw  = ncw;
    }
    #pragma unroll
    for (int j = 0; j < 6; j++) {
        int c = cbase + w + 8*j;
        float rr = re[j] + bp1_r[c];
        float ii = im[j] + bp1_i[c];
        if (lane == 0) { float2 b = g_bu0[c]; rr += b.x; ii += b.y; }
        float ga = g_gam[c*32 + lane];
        g_D[(bl*CC + c)*32 + lane] = make_float2(rr*ga, ii*ga);
    }
}

// ---------------------------------------------------------------------------
// K3: parallel LRU scan, COALESCED via shared transpose.
// Block: 256 threads, tile = 32 cu-indices x 32 l, for one b.
// grid = BB * (CC*HH/32) = 384.
//   load (lane = cu, coalesced) -> sh[l][cu] -> warp-scan (lane = l) -> store
// ---------------------------------------------------------------------------
__global__ __launch_bounds__(256) void k3_scan(const float* __restrict__ mask)
{
    __shared__ float2 sh[32*33];        // [l][cu], stride 33 (8.4 KB)
    int b   = blockIdx.x / 96;
    int cu0 = (blockIdx.x % 96) * 32;
    int tid = threadIdx.x;
    int w   = tid >> 5, lane = tid & 31;

    // load: i = l*32 + cu_loc, lanes vary cu_loc -> coalesced 256B
    #pragma unroll
    for (int k = 0; k < 4; k++) {
        int i = tid + k*256;
        int l = i >> 5, cu = i & 31;
        sh[l*33 + cu] = g_D[(b*LL + l)*(CC*HH) + cu0 + cu];
    }
    __syncthreads();

    // mask factor for this lane's l
    float mv = (lane == 0) ? 0.f : __ldg(&mask[b*LL + lane - 1]);

    // scan: warp w handles cu_loc = w*4 + j
    #pragma unroll
    for (int j = 0; j < 4; j++) {
        int cu = w*4 + j;
        float2 d   = sh[lane*33 + cu];
        float2 lam = g_lamb[cu0 + cu];          // warp-uniform
        float ar = lam.x * mv, ai = lam.y * mv;
        float dr = d.x, di = d.y;
        #pragma unroll
        for (int off = 1; off < 32; off <<= 1) {
            float par = __shfl_up_sync(0xffffffffu, ar, off);
            float pai = __shfl_up_sync(0xffffffffu, ai, off);
            float pdr = __shfl_up_sync(0xffffffffu, dr, off);
            float pdi = __shfl_up_sync(0xffffffffu, di, off);
            if (lane >= off) {
                float ndr = dr + ar*pdr - ai*pdi;
                float ndi = di + ar*pdi + ai*pdr;
                float nar = ar*par - ai*pai;
                float nai = ar*pai + ai*par;
                dr = ndr; di = ndi; ar = nar; ai = nai;
            }
        }
        sh[lane*33 + cu] = make_float2(dr, di);
    }
    __syncthreads();

    // store back, coalesced
    #pragma unroll
    for (int k = 0; k < 4; k++) {
        int i = tid + k*256;
        int l = i >> 5, cu = i & 31;
        g_D[(b*LL + l)*(CC*HH) + cu0 + cu] = sh[l*33 + cu];
    }
}

// ---------------------------------------------------------------------------
// K4: one block of 512 per (b,l). iDFT + A-mix + LN + FUSED epilogue.
//   g[c,m] = (1/1024) sum_u y[c,u] e^{+i 2pi um/32}
//   v[e,m] = Re(sum_c A[e,c] g[c,m]) + constE[e]
//   vhat   = (v - mu)*rstd   (kept in shared)
//   out[e,p,q] = vhat[e,(p+q)%32]*ln_w + ln_b + x
// ---------------------------------------------------------------------------
__global__ __launch_bounds__(512) void k4_idft_ln(const float* __restrict__ x,
                                                  const float* __restrict__ ln_w,
                                                  const float* __restrict__ ln_b,
                                                  float* __restrict__ out)
{
    __shared__ float2 y_sh[CC*32];      // 24 KB (y, then g)
    __shared__ float2 A_sh[EE*32];      // 16 KB (A chunk)
    __shared__ float  vh_sh[EE*32];     //  8 KB
    __shared__ float  red[34];
    int bl = blockIdx.x, tid = threadIdx.x;
    int w  = tid >> 5, lane = tid & 31;

    for (int i = tid; i < CC*32; i += 512) y_sh[i] = g_D[bl*CC*32 + i];
    __syncthreads();

    // --- inverse DFT: thread owns (c = w+16j, m = lane), rotation hoisted ---
    float cm, sm;
    sincospif((float)lane / 16.0f, &sm, &cm);
    float gre[6], gim[6];
    #pragma unroll
    for (int j = 0; j < 6; j++) { gre[j] = 0.f; gim[j] = 0.f; }
    float cw = 1.f, swp = 0.f;
    #pragma unroll 8
    for (int u = 0; u < 32; u++) {
        #pragma unroll
        for (int j = 0; j < 6; j++) {
            float2 y = y_sh[(w + 16*j)*32 + u];      // broadcast
            gre[j] += y.x*cw - y.y*swp;
            gim[j] += y.x*swp + y.y*cw;
        }
        float ncw = cw*cm - swp*sm;
        swp = swp*cm + cw*sm;
        cw  = ncw;
    }
    __syncthreads();
    #pragma unroll
    for (int j = 0; j < 6; j++)
        y_sh[(w + 16*j)*32 + lane] =
            make_float2(gre[j] * (1.0f/1024.0f), gim[j] * (1.0f/1024.0f));
    __syncthreads();

    // --- A-mix (real part): thread owns (e = w*4+j, m = lane), c in 3 chunks ---
    float v[4];
    #pragma unroll
    for (int j = 0; j < 4; j++) v[j] = g_cE[w*4 + j];

    #pragma unroll
    for (int ch = 0; ch < 3; ch++) {
        for (int i = tid; i < EE*32; i += 512) {
            int e = i >> 5, cc = i & 31;
            A_sh[i] = g_A[e*CC + ch*32 + cc];
        }
        __syncthreads();
        #pragma unroll 4
        for (int cc = 0; cc < 32; cc++) {
            float2 g = y_sh[(ch*32 + cc)*32 + lane];
            #pragma unroll
            for (int j = 0; j < 4; j++) {
                float2 A = A_sh[(w*4 + j)*32 + cc];  // broadcast
                v[j] += A.x*g.x - A.y*g.y;
            }
        }
        __syncthreads();
    }

    // --- LN stats over the 2048 v's ---
    float sum = 0.f, sq = 0.f;
    #pragma unroll
    for (int j = 0; j < 4; j++) { sum += v[j]; sq += v[j]*v[j]; }
    #pragma unroll
    for (int off = 16; off; off >>= 1) {
        sum += __shfl_xor_sync(0xffffffffu, sum, off);
        sq  += __shfl_xor_sync(0xffffffffu, sq , off);
    }
    if (lane == 0) { red[w] = sum; red[16 + w] = sq; }
    __syncthreads();
    if (tid == 0) {
        float s = 0.f, q = 0.f;
        #pragma unroll
        for (int i = 0; i < 16; i++) { s += red[i]; q += red[16+i]; }
        float mu  = s * (1.0f/2048.0f);
        float var = q * (1.0f/2048.0f) - mu*mu;
        red[32] = mu;
        red[33] = rsqrtf(var + 1e-5f);
    }
    __syncthreads();
    float mu = red[32], rstd = red[33];
    #pragma unroll
    for (int j = 0; j < 4; j++)
        vh_sh[(w*4 + j)*32 + lane] = (v[j] - mu) * rstd;
    __syncthreads();

    // --- fused epilogue: out = vh[e,(p+q)&31]*ln_w + ln_b + x  (float4) ---
    const float4* x4  = (const float4*)x;
    const float4* lw4 = (const float4*)ln_w;
    const float4* lb4 = (const float4*)ln_b;
    float4*       o4  = (float4*)out;
    size_t base4 = (size_t)bl * (EE*256);   // 16384 float4 per bl

    #pragma unroll
    for (int t = 0; t < 32; t++) {
        int idx4 = t*512 + tid;              // 0..16383
        int e    = idx4 >> 8;
        int r    = idx4 & 255;
        int p    = r >> 3;
        int q0   = (r & 7) * 4;

        float4 xv = x4 [base4 + idx4];
        float4 wv = lw4[(size_t)e*256 + r];
        float4 bv = lb4[(size_t)e*256 + r];
        const float* vr = &vh_sh[e*32];
        float4 ov;
        ov.x = vr[(p + q0    ) & 31]*wv.x + bv.x + xv.x;
        ov.y = vr[(p + q0 + 1) & 31]*wv.y + bv.y + xv.y;
        ov.z = vr[(p + q0 + 2) & 31]*wv.z + bv.z + xv.z;
        ov.w = vr[(p + q0 + 3) & 31]*wv.w + bv.w + xv.w;
        o4[base4 + idx4] = ov;
    }
}

// ---------------------------------------------------------------------------
extern "C" void kernel_launch(void* const* d_in, const int* in_sizes, int n_in,
                              void* d_out, int out_size)
{
    const float* x          = (const float*)d_in[0];
    const float* mask       = (const float*)d_in[1];
    const float* params_log = (const float*)d_in[2];
    const float* Wb_r  = (const float*)d_in[3],  *Wb_i  = (const float*)d_in[4];
    const float* bb_r  = (const float*)d_in[5],  *bb_i  = (const float*)d_in[6];
    const float* Wp1_r = (const float*)d_in[7],  *Wp1_i = (const float*)d_in[8];
    const float* bp1_r = (const float*)d_in[9],  *bp1_i = (const float*)d_in[10];
    const float* Wp2_r = (const float*)d_in[11], *Wp2_i = (const float*)d_in[12];
    const float* bp2_r = (const float*)d_in[13], *bp2_i = (const float*)d_in[14];
    const float* Wc_r  = (const float*)d_in[15], *Wc_i  = (const float*)d_in[16];
    const float* bc_r  = (const float*)d_in[17];   // bc_i dropped by .real
    const float* ln_w  = (const float*)d_in[19], *ln_b = (const float*)d_in[20];
    float* out = (float*)d_out;

    k0_precomp<<<CC + EE, 96>>>(Wb_r, Wb_i, bb_r, bb_i,
                                Wp1_r, Wp1_i, Wp2_r, Wp2_i,
                                Wc_r, Wc_i, bp2_r, bp2_i, bc_r, params_log);
    k1_adiag  <<<1024, 256>>>(x);
    k2_mix_dft<<<BB*LL*2, 256>>>(bp1_r, bp1_i);
    k3_scan   <<<BB*96, 256>>>(mask);
    k4_idft_ln<<<BB*LL, 512>>>(x, ln_w, ln_b, out);
}